// round 14
// baseline (speedup 1.0000x reference)
#include <cuda_runtime.h>
#include <cuda_bf16.h>
#include <math.h>
#include <stdint.h>

#define BB 32
#define NN 2048
#define DD 256

#define L2_LAMDA 0.001f
#define RECONS_LAMDA 0.2f
#define LB_TH 0.01f

// ---------------------------------------------------------------------------
// Device scratch
// ---------------------------------------------------------------------------
__device__ __nv_bfloat16 g_cur_bf[(size_t)BB * NN * DD];   // [b][n][k]
__device__ __nv_bfloat16 g_pre_bf[(size_t)BB * NN * DD];   // [b][m][d]
__device__ __nv_bfloat16 g_w_bf[(size_t)NN * NN];          // NEGATED masked incidence
__device__ __nv_bfloat16 g_r_bf[DD * DD];                  // [k][j]
__device__ float g_rowterm[NN];
__device__ float g_part[4 * BB * NN];                      // [dtile][b][n]
__device__ float g_bslice[BB * 8];                         // [b][slice] recon partial

// ---------------------------------------------------------------------------
// PTX helpers
// ---------------------------------------------------------------------------
__device__ __forceinline__ uint32_t smem_u32(const void* p) {
    uint32_t a;
    asm("{ .reg .u64 t; cvta.to.shared.u64 t, %1; cvt.u32.u64 %0, t; }"
        : "=r"(a) : "l"(p));
    return a;
}

__device__ __forceinline__ void cp16(uint32_t dst, const void* src) {
    asm volatile("cp.async.cg.shared.global [%0], [%1], 16;"
                 :: "r"(dst), "l"(src) : "memory");
}
#define CP_COMMIT() asm volatile("cp.async.commit_group;" ::: "memory")

__device__ __forceinline__ void ldsm_x4(uint32_t& r0, uint32_t& r1,
                                        uint32_t& r2, uint32_t& r3, uint32_t addr) {
    asm volatile("ldmatrix.sync.aligned.m8n8.x4.shared.b16 {%0,%1,%2,%3}, [%4];"
                 : "=r"(r0), "=r"(r1), "=r"(r2), "=r"(r3) : "r"(addr));
}
__device__ __forceinline__ void ldsm_x4t(uint32_t& r0, uint32_t& r1,
                                         uint32_t& r2, uint32_t& r3, uint32_t addr) {
    asm volatile("ldmatrix.sync.aligned.m8n8.x4.trans.shared.b16 {%0,%1,%2,%3}, [%4];"
                 : "=r"(r0), "=r"(r1), "=r"(r2), "=r"(r3) : "r"(addr));
}

__device__ __forceinline__ void mma16816(float* d, const uint32_t* a, const uint32_t* b) {
    asm volatile(
        "mma.sync.aligned.m16n8k16.row.col.f32.bf16.bf16.f32 "
        "{%0,%1,%2,%3}, {%4,%5,%6,%7}, {%8,%9}, {%0,%1,%2,%3};"
        : "+f"(d[0]), "+f"(d[1]), "+f"(d[2]), "+f"(d[3])
        : "r"(a[0]), "r"(a[1]), "r"(a[2]), "r"(a[3]), "r"(b[0]), "r"(b[1]));
}

#define SWZ(o) ((uint32_t)(o) ^ ((((uint32_t)(o)) >> 3) & 0x70))

__device__ __forceinline__ uint32_t bf2u(float x, float y) {
    __nv_bfloat162 t = __floats2bfloat162_rn(x, y);
    return *(uint32_t*)&t;
}

// ---------------------------------------------------------------------------
// Merged prep kernel (proven in R13).
// ---------------------------------------------------------------------------
#define NG_BIG (BB * NN * DD / 8)      // 2,097,152
#define INC_BLOCKS 256
#define R_BLOCKS   (DD * DD / 8 / 256) // 32
#define BIG_BLOCKS (2 * NG_BIG / 256)  // 16,384
#define PREP_GRID  (INC_BLOCKS + R_BLOCKS + BIG_BLOCKS)   // 16,672

__global__ __launch_bounds__(256) void prep_kernel(const float4* __restrict__ cur,
                                                   const float4* __restrict__ pre,
                                                   const float4* __restrict__ rproj,
                                                   const float* __restrict__ inc,
                                                   float* __restrict__ outinc) {
    const int bid = blockIdx.x;
    const int tid = threadIdx.x;

    if (bid < INC_BLOCKS) {
        const int lane = tid & 31;
        const int warp = tid >> 5;
        const int n = bid * 8 + warp;
        const float4* row = (const float4*)(inc + (size_t)n * NN);
        __nv_bfloat162* wrow = (__nv_bfloat162*)(g_w_bf + (size_t)n * NN);
        float4* orow = outinc ? ((float4*)outinc) + (size_t)n * (NN / 4) : nullptr;

        float mx = 0.0f, sq = 0.0f;
#pragma unroll
        for (int j = 0; j < 16; j++) {
            int i = lane + j * 32;
            float4 v = row[i];
            if (orow) orow[i] = v;
            float a = (v.x > LB_TH) ? v.x : 0.0f;
            float b = (v.y > LB_TH) ? v.y : 0.0f;
            float c = (v.z > LB_TH) ? v.z : 0.0f;
            float d = (v.w > LB_TH) ? v.w : 0.0f;
            mx = fmaxf(mx, fmaxf(fmaxf(a, b), fmaxf(c, d)));
            sq += a * a + b * b + c * c + d * d;
            wrow[2 * i]     = __floats2bfloat162_rn(-a, -b);
            wrow[2 * i + 1] = __floats2bfloat162_rn(-c, -d);
        }
#pragma unroll
        for (int s = 16; s > 0; s >>= 1) {
            mx = fmaxf(mx, __shfl_xor_sync(0xFFFFFFFF, mx, s));
            sq += __shfl_xor_sync(0xFFFFFFFF, sq, s);
        }
        if (lane == 0) g_rowterm[n] = mx + L2_LAMDA * sqrtf(sq);
    } else if (bid < INC_BLOCKS + R_BLOCKS) {
        const int g = (bid - INC_BLOCKS) * 256 + tid;
        float4 v0 = rproj[2 * g];
        float4 v1 = rproj[2 * g + 1];
        ((uint4*)g_r_bf)[g] = make_uint4(bf2u(v0.x, v0.y), bf2u(v0.z, v0.w),
                                         bf2u(v1.x, v1.y), bf2u(v1.z, v1.w));
    } else {
        int g = (bid - INC_BLOCKS - R_BLOCKS) * 256 + tid;
        const float4* src;
        uint4* dst;
        if (g < NG_BIG) { src = cur; dst = (uint4*)g_cur_bf; }
        else            { src = pre; dst = (uint4*)g_pre_bf; g -= NG_BIG; }
        float4 v0 = src[2 * g];
        float4 v1 = src[2 * g + 1];
        dst[g] = make_uint4(bf2u(v0.x, v0.y), bf2u(v0.z, v0.w),
                            bf2u(v1.x, v1.y), bf2u(v1.z, v1.w));
    }
}

// ---------------------------------------------------------------------------
// Main GEMM: per CTA (dtile 0..3, ntile 0..15, b), 128(n) x 64(d) tile of
//   diff = cur_b @ R + (-W) @ pre_b
// 4 warps, each 64(rows) x 32(cols): acc = 64 regs -> occ 3 target.
// A smem: 128 rows x 128B K-major SW128 (16KB).
// B smem: 64 k-rows x 128B trans layout, seg ^= (krow & 7)  (8KB).
// 3-stage cp.async pipeline (24KB/stage, 72KB total -> 3 CTAs/SM).
// ---------------------------------------------------------------------------
#define CHUNKS 36            // 4 (cur@R, K=256) + 32 (W@pre, K=2048)
#define STAGE_BYTES 24576    // 16KB A + 8KB B
#define NSTAGE 3
#define GEMM_SMEM (NSTAGE * STAGE_BYTES)   // 73728

__global__ __launch_bounds__(128, 3) void gemm_kernel() {
    extern __shared__ char smem[];
    const uint32_t sb = smem_u32(smem);
    const int tid = threadIdx.x;
    const int lane = tid & 31;
    const int w = tid >> 5;          // 0..3
    const int warp_m = w & 1;        // 64-row half
    const int warp_n = w >> 1;       // 32-col half

    const int dtile = blockIdx.x;    // 0..3
    const int ntile = blockIdx.y;    // 0..15
    const int b     = blockIdx.z;    // 0..31
    const int n0 = ntile * 128;
    const int d0 = dtile * 64;

    float acc[4][4][4];
#pragma unroll
    for (int mt = 0; mt < 4; mt++)
#pragma unroll
        for (int nt = 0; nt < 4; nt++)
#pragma unroll
            for (int i = 0; i < 4; i++) acc[mt][nt][i] = 0.0f;

    uint32_t arow[4];
#pragma unroll
    for (int mt = 0; mt < 4; mt++)
        arow[mt] = (uint32_t)(warp_m * 64 + mt * 16 + (lane & 15)) * 128;
    const uint32_t alx = (lane & 7);
    const uint32_t ahi = (lane >> 4);
    // B (trans) fragments: 128B k-rows (8 segs); cb = warp_n*4 + jg*2 + (lane>>4)
    uint32_t btb[2];
#pragma unroll
    for (int jg = 0; jg < 2; jg++) {
        uint32_t cb = (uint32_t)(warp_n * 4 + jg * 2) + (lane >> 4);
        btb[jg] = (uint32_t)(lane & 15) * 128 + ((cb ^ (lane & 7)) << 4);
    }

    const __nv_bfloat16* curb = g_cur_bf + ((size_t)b * NN + n0) * DD;
    const __nv_bfloat16* preb = g_pre_bf + (size_t)b * NN * DD + d0;
    const __nv_bfloat16* wb   = g_w_bf + (size_t)n0 * NN;
    const __nv_bfloat16* rb   = g_r_bf + d0;

    // A: 128 rows x 128B = 1024 cp16 (8/thread). B: 64 rows x 8 segs = 512 (4/thread).
#define LOAD_KM(dst, src, ld)                                                   \
    _Pragma("unroll")                                                           \
    for (int i = 0; i < 8; i++) {                                               \
        int o = tid + i * 128;                                                  \
        int row = o >> 3, seg = o & 7;                                          \
        cp16((dst) + SWZ(row * 128 + seg * 16),                                 \
             (src) + (size_t)row * (ld) + seg * 8);                             \
    }
#define LOAD_TR(dst, src, ld)                                                   \
    _Pragma("unroll")                                                           \
    for (int i = 0; i < 4; i++) {                                               \
        int o = tid + i * 128;                                                  \
        int row = o >> 3, seg = o & 7;                                          \
        cp16((dst) + row * 128 + (((seg ^ (row & 7))) << 4),                    \
             (src) + (size_t)row * (ld) + seg * 8);                             \
    }

#define LOAD_CHUNK(c)                                                           \
    {                                                                           \
        const uint32_t st = sb + ((c) % NSTAGE) * STAGE_BYTES;                  \
        if ((c) < 4) {                                                          \
            int k0 = (c) * 64;                                                  \
            LOAD_KM(st, curb + k0, DD);                                         \
            LOAD_TR(st + 16384, rb + (size_t)k0 * DD, DD);                      \
        } else {                                                                \
            int k0 = ((c) - 4) * 64;                                            \
            LOAD_KM(st, wb + k0, NN);                                           \
            LOAD_TR(st + 16384, preb + (size_t)k0 * DD, DD);                    \
        }                                                                       \
        CP_COMMIT();                                                            \
    }

    LOAD_CHUNK(0);
    LOAD_CHUNK(1);

    for (int c = 0; c < CHUNKS; c++) {
        if (c + 1 < CHUNKS)
            asm volatile("cp.async.wait_group 1;" ::: "memory");
        else
            asm volatile("cp.async.wait_group 0;" ::: "memory");
        __syncthreads();

        if (c + 2 < CHUNKS) LOAD_CHUNK(c + 2);

        const uint32_t sA = sb + (uint32_t)(c % NSTAGE) * STAGE_BYTES;
        const uint32_t sB = sA + 16384;

#pragma unroll
        for (int s = 0; s < 4; s++) {
            const uint32_t ch = (uint32_t)(s * 2) + ahi;
            const uint32_t csw = (ch ^ alx) << 4;
            uint32_t a[4][4];
#pragma unroll
            for (int mt = 0; mt < 4; mt++)
                ldsm_x4(a[mt][0], a[mt][1], a[mt][2], a[mt][3],
                        sA + arow[mt] + csw);
            uint32_t bf[4][2];
#pragma unroll
            for (int jg = 0; jg < 2; jg++)
                ldsm_x4t(bf[2 * jg][0], bf[2 * jg][1],
                         bf[2 * jg + 1][0], bf[2 * jg + 1][1],
                         sB + s * 2048 + btb[jg]);
#pragma unroll
            for (int mt = 0; mt < 4; mt++)
#pragma unroll
                for (int nt = 0; nt < 4; nt++)
                    mma16816(acc[mt][nt], a[mt], bf[nt]);
        }
    }

    // ------------- epilogue: per-row sum of squares over 64 cols -------------
    __shared__ float red[128][2];
#pragma unroll
    for (int mt = 0; mt < 4; mt++) {
        float s0 = 0.0f, s1 = 0.0f;
#pragma unroll
        for (int nt = 0; nt < 4; nt++) {
            s0 = fmaf(acc[mt][nt][0], acc[mt][nt][0], s0);
            s0 = fmaf(acc[mt][nt][1], acc[mt][nt][1], s0);
            s1 = fmaf(acc[mt][nt][2], acc[mt][nt][2], s1);
            s1 = fmaf(acc[mt][nt][3], acc[mt][nt][3], s1);
        }
        s0 += __shfl_xor_sync(0xFFFFFFFF, s0, 1);
        s0 += __shfl_xor_sync(0xFFFFFFFF, s0, 2);
        s1 += __shfl_xor_sync(0xFFFFFFFF, s1, 1);
        s1 += __shfl_xor_sync(0xFFFFFFFF, s1, 2);
        if ((lane & 3) == 0) {
            int r = warp_m * 64 + mt * 16 + (lane >> 2);
            red[r][warp_n] = s0;
            red[r + 8][warp_n] = s1;
        }
    }
    __syncthreads();
    g_part[((size_t)dtile * BB + b) * NN + n0 + tid] = red[tid][0] + red[tid][1];
}

// ---------------------------------------------------------------------------
// Finalize phase 1: 256 CTAs = (b, slice); sums sqrt over 4 dtile partials.
// ---------------------------------------------------------------------------
__global__ __launch_bounds__(256) void fin1_kernel() {
    const int b = blockIdx.x >> 3;
    const int slice = blockIdx.x & 7;
    const int tid = threadIdx.x;
    const int n = slice * 256 + tid;

    float t = g_part[(size_t)b * NN + n]
            + g_part[((size_t)BB + b) * NN + n]
            + g_part[((size_t)2 * BB + b) * NN + n]
            + g_part[((size_t)3 * BB + b) * NN + n];
    float v = sqrtf(t);

    const int lane = tid & 31;
    const int warp = tid >> 5;
#pragma unroll
    for (int s = 16; s > 0; s >>= 1) v += __shfl_xor_sync(0xFFFFFFFF, v, s);
    __shared__ float sm[8];
    if (lane == 0) sm[warp] = v;
    __syncthreads();
    if (tid == 0) {
        float u = 0.0f;
#pragma unroll
        for (int i = 0; i < 8; i++) u += sm[i];
        g_bslice[blockIdx.x] = u;
    }
}

// ---------------------------------------------------------------------------
// Finalize phase 2: 1 CTA.
// ---------------------------------------------------------------------------
__global__ __launch_bounds__(256) void fin2_kernel(float* __restrict__ out) {
    const int tid = threadIdx.x;
    const int lane = tid & 31;
    const int warp = tid >> 5;

    float r = 0.0f;
#pragma unroll
    for (int j = 0; j < 8; j++) r += g_rowterm[tid + j * 256];
#pragma unroll
    for (int s = 16; s > 0; s >>= 1) r += __shfl_xor_sync(0xFFFFFFFF, r, s);
    __shared__ float sm[8];
    __shared__ float rowsum_s;
    if (lane == 0) sm[warp] = r;
    __syncthreads();
    if (tid == 0) {
        float t = 0.0f;
#pragma unroll
        for (int i = 0; i < 8; i++) t += sm[i];
        rowsum_s = t;
    }
    __syncthreads();
    if (tid < BB) {
        float s = 0.0f;
#pragma unroll
        for (int k = 0; k < 8; k++) s += g_bslice[tid * 8 + k];
        out[tid] = RECONS_LAMDA * s + rowsum_s;
    }
}

// ---------------------------------------------------------------------------
extern "C" void kernel_launch(void* const* d_in, const int* in_sizes, int n_in,
                              void* d_out, int out_size) {
    const float* cur = nullptr;
    const float* pre = nullptr;
    const float* rproj = nullptr;
    const float* inc = nullptr;
    int big_seen = 0;
    for (int i = 0; i < n_in; i++) {
        if (in_sizes[i] == DD * DD) rproj = (const float*)d_in[i];
        else if (in_sizes[i] == NN * NN) inc = (const float*)d_in[i];
        else if (in_sizes[i] == BB * NN * DD) {
            if (big_seen == 0) cur = (const float*)d_in[i];
            else pre = (const float*)d_in[i];
            big_seen++;
        }
    }
    float* out = (float*)d_out;
    float* outinc = (out_size >= BB + NN * NN) ? (out + BB) : nullptr;

    cudaFuncSetAttribute(gemm_kernel, cudaFuncAttributeMaxDynamicSharedMemorySize, GEMM_SMEM);

    prep_kernel<<<PREP_GRID, 256>>>((const float4*)cur, (const float4*)pre,
                                    (const float4*)rproj, inc, outinc);       // 1
    gemm_kernel<<<dim3(4, 16, BB), 128, GEMM_SMEM>>>();                       // 2
    fin1_kernel<<<BB * 8, 256>>>();                                           // 3
    fin2_kernel<<<1, 256>>>(out);                                             // 4
}

// round 15
// speedup vs baseline: 1.0138x; 1.0138x over previous
#include <cuda_runtime.h>
#include <cuda_bf16.h>
#include <math.h>
#include <stdint.h>

#define BB 32
#define NN 2048
#define DD 256

#define L2_LAMDA 0.001f
#define RECONS_LAMDA 0.2f
#define LB_TH 0.01f

// ---------------------------------------------------------------------------
// Device scratch
// ---------------------------------------------------------------------------
__device__ __nv_bfloat16 g_cur_bf[(size_t)BB * NN * DD];   // [b][n][k]
__device__ __nv_bfloat16 g_pre_bf[(size_t)BB * NN * DD];   // [b][m][d]
__device__ __nv_bfloat16 g_w_bf[(size_t)NN * NN];          // NEGATED masked incidence
__device__ __nv_bfloat16 g_r_bf[DD * DD];                  // [k][j]
__device__ float g_rowterm[NN];
__device__ float g_part[2 * BB * NN];                      // [dtile][b][n]

// ---------------------------------------------------------------------------
// PTX helpers
// ---------------------------------------------------------------------------
__device__ __forceinline__ uint32_t smem_u32(const void* p) {
    uint32_t a;
    asm("{ .reg .u64 t; cvta.to.shared.u64 t, %1; cvt.u32.u64 %0, t; }"
        : "=r"(a) : "l"(p));
    return a;
}

__device__ __forceinline__ void cp16(uint32_t dst, const void* src) {
    asm volatile("cp.async.cg.shared.global [%0], [%1], 16;"
                 :: "r"(dst), "l"(src) : "memory");
}
#define CP_COMMIT() asm volatile("cp.async.commit_group;" ::: "memory")

__device__ __forceinline__ void ldsm_x4(uint32_t& r0, uint32_t& r1,
                                        uint32_t& r2, uint32_t& r3, uint32_t addr) {
    asm volatile("ldmatrix.sync.aligned.m8n8.x4.shared.b16 {%0,%1,%2,%3}, [%4];"
                 : "=r"(r0), "=r"(r1), "=r"(r2), "=r"(r3) : "r"(addr));
}
__device__ __forceinline__ void ldsm_x4t(uint32_t& r0, uint32_t& r1,
                                         uint32_t& r2, uint32_t& r3, uint32_t addr) {
    asm volatile("ldmatrix.sync.aligned.m8n8.x4.trans.shared.b16 {%0,%1,%2,%3}, [%4];"
                 : "=r"(r0), "=r"(r1), "=r"(r2), "=r"(r3) : "r"(addr));
}

__device__ __forceinline__ void mma16816(float* d, const uint32_t* a, const uint32_t* b) {
    asm volatile(
        "mma.sync.aligned.m16n8k16.row.col.f32.bf16.bf16.f32 "
        "{%0,%1,%2,%3}, {%4,%5,%6,%7}, {%8,%9}, {%0,%1,%2,%3};"
        : "+f"(d[0]), "+f"(d[1]), "+f"(d[2]), "+f"(d[3])
        : "r"(a[0]), "r"(a[1]), "r"(a[2]), "r"(a[3]), "r"(b[0]), "r"(b[1]));
}

#define SWZ(o) ((uint32_t)(o) ^ ((((uint32_t)(o)) >> 3) & 0x70))

__device__ __forceinline__ uint32_t bf2u(float x, float y) {
    __nv_bfloat162 t = __floats2bfloat162_rn(x, y);
    return *(uint32_t*)&t;
}

// ---------------------------------------------------------------------------
// Merged prep kernel (proven in R13).
//   [0, 256)        : inc -> masked/negated bf16 W + rowterm + passthrough out
//   [256, 288)      : R   -> bf16
//   [288, 16672)    : cur | pre -> bf16
// ---------------------------------------------------------------------------
#define NG_BIG (BB * NN * DD / 8)      // 2,097,152
#define INC_BLOCKS 256
#define R_BLOCKS   (DD * DD / 8 / 256) // 32
#define BIG_BLOCKS (2 * NG_BIG / 256)  // 16,384
#define PREP_GRID  (INC_BLOCKS + R_BLOCKS + BIG_BLOCKS)   // 16,672

__global__ __launch_bounds__(256) void prep_kernel(const float4* __restrict__ cur,
                                                   const float4* __restrict__ pre,
                                                   const float4* __restrict__ rproj,
                                                   const float* __restrict__ inc,
                                                   float* __restrict__ outinc) {
    const int bid = blockIdx.x;
    const int tid = threadIdx.x;

    if (bid < INC_BLOCKS) {
        const int lane = tid & 31;
        const int warp = tid >> 5;
        const int n = bid * 8 + warp;
        const float4* row = (const float4*)(inc + (size_t)n * NN);
        __nv_bfloat162* wrow = (__nv_bfloat162*)(g_w_bf + (size_t)n * NN);
        float4* orow = outinc ? ((float4*)outinc) + (size_t)n * (NN / 4) : nullptr;

        float mx = 0.0f, sq = 0.0f;
#pragma unroll
        for (int j = 0; j < 16; j++) {
            int i = lane + j * 32;
            float4 v = row[i];
            if (orow) orow[i] = v;
            float a = (v.x > LB_TH) ? v.x : 0.0f;
            float b = (v.y > LB_TH) ? v.y : 0.0f;
            float c = (v.z > LB_TH) ? v.z : 0.0f;
            float d = (v.w > LB_TH) ? v.w : 0.0f;
            mx = fmaxf(mx, fmaxf(fmaxf(a, b), fmaxf(c, d)));
            sq += a * a + b * b + c * c + d * d;
            wrow[2 * i]     = __floats2bfloat162_rn(-a, -b);
            wrow[2 * i + 1] = __floats2bfloat162_rn(-c, -d);
        }
#pragma unroll
        for (int s = 16; s > 0; s >>= 1) {
            mx = fmaxf(mx, __shfl_xor_sync(0xFFFFFFFF, mx, s));
            sq += __shfl_xor_sync(0xFFFFFFFF, sq, s);
        }
        if (lane == 0) g_rowterm[n] = mx + L2_LAMDA * sqrtf(sq);
    } else if (bid < INC_BLOCKS + R_BLOCKS) {
        const int g = (bid - INC_BLOCKS) * 256 + tid;
        float4 v0 = rproj[2 * g];
        float4 v1 = rproj[2 * g + 1];
        ((uint4*)g_r_bf)[g] = make_uint4(bf2u(v0.x, v0.y), bf2u(v0.z, v0.w),
                                         bf2u(v1.x, v1.y), bf2u(v1.z, v1.w));
    } else {
        int g = (bid - INC_BLOCKS - R_BLOCKS) * 256 + tid;
        const float4* src;
        uint4* dst;
        if (g < NG_BIG) { src = cur; dst = (uint4*)g_cur_bf; }
        else            { src = pre; dst = (uint4*)g_pre_bf; g -= NG_BIG; }
        float4 v0 = src[2 * g];
        float4 v1 = src[2 * g + 1];
        dst[g] = make_uint4(bf2u(v0.x, v0.y), bf2u(v0.z, v0.w),
                            bf2u(v1.x, v1.y), bf2u(v1.z, v1.w));
    }
}

// ---------------------------------------------------------------------------
// Main GEMM (R13-proven config, byte-identical): per CTA (dtile, ntile, b),
// 128x128 tile: diff = cur_b @ R + (-W) @ pre_b
// 4 warps, each 64x64. 3-stage cp.async pipeline, ONE __syncthreads per chunk.
// ---------------------------------------------------------------------------
#define CHUNKS 36            // 4 (cur@R, K=256) + 32 (W@pre, K=2048)
#define STAGE_BYTES 32768    // 16KB A + 16KB B
#define NSTAGE 3
#define GEMM_SMEM (NSTAGE * STAGE_BYTES)   // 96KB; x2 CTAs = 192KB

__global__ __launch_bounds__(128, 2) void gemm_kernel() {
    extern __shared__ char smem[];
    const uint32_t sb = smem_u32(smem);
    const int tid = threadIdx.x;
    const int lane = tid & 31;
    const int w = tid >> 5;          // 0..3
    const int warp_m = w & 1;        // 64-row half
    const int warp_n = w >> 1;       // 64-col half

    const int dtile = blockIdx.x;    // 0..1
    const int ntile = blockIdx.y;    // 0..15
    const int b     = blockIdx.z;    // 0..31
    const int n0 = ntile * 128;
    const int d0 = dtile * 128;

    float acc[4][8][4];
#pragma unroll
    for (int mt = 0; mt < 4; mt++)
#pragma unroll
        for (int nt = 0; nt < 8; nt++)
#pragma unroll
            for (int i = 0; i < 4; i++) acc[mt][nt][i] = 0.0f;

    uint32_t arow[4];
#pragma unroll
    for (int mt = 0; mt < 4; mt++)
        arow[mt] = (uint32_t)(warp_m * 64 + mt * 16 + (lane & 15)) * 128;
    const uint32_t alx = (lane & 7);
    const uint32_t ahi = (lane >> 4);
    uint32_t btb[4];
#pragma unroll
    for (int jg = 0; jg < 4; jg++) {
        uint32_t cb = (uint32_t)(warp_n * 8 + jg * 2) + (lane >> 4);
        btb[jg] = (uint32_t)(lane & 15) * 256 + ((cb ^ (lane & 7)) << 4);
    }

    const __nv_bfloat16* curb = g_cur_bf + ((size_t)b * NN + n0) * DD;
    const __nv_bfloat16* preb = g_pre_bf + (size_t)b * NN * DD + d0;
    const __nv_bfloat16* wb   = g_w_bf + (size_t)n0 * NN;
    const __nv_bfloat16* rb   = g_r_bf + d0;

#define LOAD_KM(dst, src, ld)                                                   \
    _Pragma("unroll")                                                           \
    for (int i = 0; i < 8; i++) {                                               \
        int o = tid + i * 128;                                                  \
        int row = o >> 3, seg = o & 7;                                          \
        cp16((dst) + SWZ(row * 128 + seg * 16),                                 \
             (src) + (size_t)row * (ld) + seg * 8);                             \
    }
#define LOAD_TR(dst, src, ld)                                                   \
    _Pragma("unroll")                                                           \
    for (int i = 0; i < 8; i++) {                                               \
        int o = tid + i * 128;                                                  \
        int row = o >> 4, seg = o & 15;                                         \
        cp16((dst) + row * 256 + (((seg ^ (row & 7))) << 4),                    \
             (src) + (size_t)row * (ld) + seg * 8);                             \
    }

#define LOAD_CHUNK(c)                                                           \
    {                                                                           \
        const uint32_t st = sb + ((c) % NSTAGE) * STAGE_BYTES;                  \
        if ((c) < 4) {                                                          \
            int k0 = (c) * 64;                                                  \
            LOAD_KM(st, curb + k0, DD);                                         \
            LOAD_TR(st + 16384, rb + (size_t)k0 * DD, DD);                      \
        } else {                                                                \
            int k0 = ((c) - 4) * 64;                                            \
            LOAD_KM(st, wb + k0, NN);                                           \
            LOAD_TR(st + 16384, preb + (size_t)k0 * DD, DD);                    \
        }                                                                       \
        CP_COMMIT();                                                            \
    }

    LOAD_CHUNK(0);
    LOAD_CHUNK(1);

    for (int c = 0; c < CHUNKS; c++) {
        if (c + 1 < CHUNKS)
            asm volatile("cp.async.wait_group 1;" ::: "memory");
        else
            asm volatile("cp.async.wait_group 0;" ::: "memory");
        __syncthreads();

        if (c + 2 < CHUNKS) LOAD_CHUNK(c + 2);

        const uint32_t sA = sb + (uint32_t)(c % NSTAGE) * STAGE_BYTES;
        const uint32_t sB = sA + 16384;

#pragma unroll
        for (int s = 0; s < 4; s++) {
            const uint32_t ch = (uint32_t)(s * 2) + ahi;
            const uint32_t csw = (ch ^ alx) << 4;
            uint32_t a[4][4];
#pragma unroll
            for (int mt = 0; mt < 4; mt++)
                ldsm_x4(a[mt][0], a[mt][1], a[mt][2], a[mt][3],
                        sA + arow[mt] + csw);
            uint32_t bf[8][2];
#pragma unroll
            for (int jg = 0; jg < 4; jg++)
                ldsm_x4t(bf[2 * jg][0], bf[2 * jg][1],
                         bf[2 * jg + 1][0], bf[2 * jg + 1][1],
                         sB + s * 4096 + btb[jg]);
#pragma unroll
            for (int mt = 0; mt < 4; mt++)
#pragma unroll
                for (int nt = 0; nt < 8; nt++)
                    mma16816(acc[mt][nt], a[mt], bf[nt]);
        }
    }

    // ------------- epilogue: per-row sum of squares -------------
    __shared__ float red[128][2];
#pragma unroll
    for (int mt = 0; mt < 4; mt++) {
        float s0 = 0.0f, s1 = 0.0f;
#pragma unroll
        for (int nt = 0; nt < 8; nt++) {
            s0 = fmaf(acc[mt][nt][0], acc[mt][nt][0], s0);
            s0 = fmaf(acc[mt][nt][1], acc[mt][nt][1], s0);
            s1 = fmaf(acc[mt][nt][2], acc[mt][nt][2], s1);
            s1 = fmaf(acc[mt][nt][3], acc[mt][nt][3], s1);
        }
        s0 += __shfl_xor_sync(0xFFFFFFFF, s0, 1);
        s0 += __shfl_xor_sync(0xFFFFFFFF, s0, 2);
        s1 += __shfl_xor_sync(0xFFFFFFFF, s1, 1);
        s1 += __shfl_xor_sync(0xFFFFFFFF, s1, 2);
        if ((lane & 3) == 0) {
            int r = warp_m * 64 + mt * 16 + (lane >> 2);
            red[r][warp_n] = s0;
            red[r + 8][warp_n] = s1;
        }
    }
    __syncthreads();
    g_part[((size_t)dtile * BB + b) * NN + n0 + tid] = red[tid][0] + red[tid][1];
}

// ---------------------------------------------------------------------------
// Single finalize: 32 CTAs (one per b) x 1024 threads, 2 rows per thread.
// Each CTA also (redundantly, in identical order) reduces rowterm.
// out[b] = 0.2 * sum_n sqrt(part0+part1) + sum_n rowterm
// ---------------------------------------------------------------------------
__global__ __launch_bounds__(1024) void fin_kernel(float* __restrict__ out) {
    const int b = blockIdx.x;
    const int tid = threadIdx.x;
    const int lane = tid & 31;
    const int warp = tid >> 5;

    const float* p0 = g_part + (size_t)b * NN;
    const float* p1 = g_part + ((size_t)BB + b) * NN;

    float v = sqrtf(p0[tid] + p1[tid]) + sqrtf(p0[tid + 1024] + p1[tid + 1024]);
    float r = g_rowterm[tid] + g_rowterm[tid + 1024];

#pragma unroll
    for (int s = 16; s > 0; s >>= 1) {
        v += __shfl_xor_sync(0xFFFFFFFF, v, s);
        r += __shfl_xor_sync(0xFFFFFFFF, r, s);
    }
    __shared__ float sv[32];
    __shared__ float sr[32];
    if (lane == 0) { sv[warp] = v; sr[warp] = r; }
    __syncthreads();
    if (warp == 0) {
        float tv = sv[lane];
        float tr = sr[lane];
#pragma unroll
        for (int s = 16; s > 0; s >>= 1) {
            tv += __shfl_xor_sync(0xFFFFFFFF, tv, s);
            tr += __shfl_xor_sync(0xFFFFFFFF, tr, s);
        }
        if (lane == 0) out[b] = RECONS_LAMDA * tv + tr;
    }
}

// ---------------------------------------------------------------------------
extern "C" void kernel_launch(void* const* d_in, const int* in_sizes, int n_in,
                              void* d_out, int out_size) {
    const float* cur = nullptr;
    const float* pre = nullptr;
    const float* rproj = nullptr;
    const float* inc = nullptr;
    int big_seen = 0;
    for (int i = 0; i < n_in; i++) {
        if (in_sizes[i] == DD * DD) rproj = (const float*)d_in[i];
        else if (in_sizes[i] == NN * NN) inc = (const float*)d_in[i];
        else if (in_sizes[i] == BB * NN * DD) {
            if (big_seen == 0) cur = (const float*)d_in[i];
            else pre = (const float*)d_in[i];
            big_seen++;
        }
    }
    float* out = (float*)d_out;
    float* outinc = (out_size >= BB + NN * NN) ? (out + BB) : nullptr;

    cudaFuncSetAttribute(gemm_kernel, cudaFuncAttributeMaxDynamicSharedMemorySize, GEMM_SMEM);

    prep_kernel<<<PREP_GRID, 256>>>((const float4*)cur, (const float4*)pre,
                                    (const float4*)rproj, inc, outinc);       // 1
    gemm_kernel<<<dim3(2, 16, BB), 128, GEMM_SMEM>>>();                       // 2
    fin_kernel<<<BB, 1024>>>(out);                                            // 3
}

// round 17
// speedup vs baseline: 1.0165x; 1.0027x over previous
#include <cuda_runtime.h>
#include <cuda_bf16.h>
#include <math.h>
#include <stdint.h>

#define BB 32
#define NN 2048
#define DD 256

#define L2_LAMDA 0.001f
#define RECONS_LAMDA 0.2f
#define LB_TH 0.01f

// ---------------------------------------------------------------------------
// Device scratch
// ---------------------------------------------------------------------------
__device__ __nv_bfloat16 g_cur_bf[(size_t)BB * NN * DD];   // [b][n][k]
__device__ __nv_bfloat16 g_pre_bf[(size_t)BB * NN * DD];   // [b][m][d]
__device__ __nv_bfloat16 g_w_bf[(size_t)NN * NN];          // NEGATED masked incidence
__device__ __nv_bfloat16 g_r_bf[DD * DD];                  // [k][j]
__device__ float g_rowterm[NN];
__device__ float g_part[2 * BB * NN];                      // [dtile][b][n]

// ---------------------------------------------------------------------------
// PTX helpers
// ---------------------------------------------------------------------------
__device__ __forceinline__ uint32_t smem_u32(const void* p) {
    uint32_t a;
    asm("{ .reg .u64 t; cvta.to.shared.u64 t, %1; cvt.u32.u64 %0, t; }"
        : "=r"(a) : "l"(p));
    return a;
}

__device__ __forceinline__ void cp16(uint32_t dst, const void* src) {
    asm volatile("cp.async.cg.shared.global [%0], [%1], 16;"
                 :: "r"(dst), "l"(src) : "memory");
}
#define CP_COMMIT() asm volatile("cp.async.commit_group;" ::: "memory")

__device__ __forceinline__ void ldsm_x4(uint32_t& r0, uint32_t& r1,
                                        uint32_t& r2, uint32_t& r3, uint32_t addr) {
    asm volatile("ldmatrix.sync.aligned.m8n8.x4.shared.b16 {%0,%1,%2,%3}, [%4];"
                 : "=r"(r0), "=r"(r1), "=r"(r2), "=r"(r3) : "r"(addr));
}
__device__ __forceinline__ void ldsm_x4t(uint32_t& r0, uint32_t& r1,
                                         uint32_t& r2, uint32_t& r3, uint32_t addr) {
    asm volatile("ldmatrix.sync.aligned.m8n8.x4.trans.shared.b16 {%0,%1,%2,%3}, [%4];"
                 : "=r"(r0), "=r"(r1), "=r"(r2), "=r"(r3) : "r"(addr));
}

__device__ __forceinline__ void mma16816(float* d, const uint32_t* a, const uint32_t* b) {
    asm volatile(
        "mma.sync.aligned.m16n8k16.row.col.f32.bf16.bf16.f32 "
        "{%0,%1,%2,%3}, {%4,%5,%6,%7}, {%8,%9}, {%0,%1,%2,%3};"
        : "+f"(d[0]), "+f"(d[1]), "+f"(d[2]), "+f"(d[3])
        : "r"(a[0]), "r"(a[1]), "r"(a[2]), "r"(a[3]), "r"(b[0]), "r"(b[1]));
}

#define SWZ(o) ((uint32_t)(o) ^ ((((uint32_t)(o)) >> 3) & 0x70))

__device__ __forceinline__ uint32_t bf2u(float x, float y) {
    __nv_bfloat162 t = __floats2bfloat162_rn(x, y);
    return *(uint32_t*)&t;
}

// ---------------------------------------------------------------------------
// Merged prep kernel (proven in R13/R15).
//   [0, 256)        : inc -> masked/negated bf16 W + rowterm + passthrough out
//   [256, 288)      : R   -> bf16
//   [288, 16672)    : cur | pre -> bf16
// ---------------------------------------------------------------------------
#define NG_BIG (BB * NN * DD / 8)      // 2,097,152
#define INC_BLOCKS 256
#define R_BLOCKS   (DD * DD / 8 / 256) // 32
#define BIG_BLOCKS (2 * NG_BIG / 256)  // 16,384
#define PREP_GRID  (INC_BLOCKS + R_BLOCKS + BIG_BLOCKS)   // 16,672

__global__ __launch_bounds__(256) void prep_kernel(const float4* __restrict__ cur,
                                                   const float4* __restrict__ pre,
                                                   const float4* __restrict__ rproj,
                                                   const float* __restrict__ inc,
                                                   float* __restrict__ outinc) {
    const int bid = blockIdx.x;
    const int tid = threadIdx.x;

    if (bid < INC_BLOCKS) {
        const int lane = tid & 31;
        const int warp = tid >> 5;
        const int n = bid * 8 + warp;
        const float4* row = (const float4*)(inc + (size_t)n * NN);
        __nv_bfloat162* wrow = (__nv_bfloat162*)(g_w_bf + (size_t)n * NN);
        float4* orow = outinc ? ((float4*)outinc) + (size_t)n * (NN / 4) : nullptr;

        float mx = 0.0f, sq = 0.0f;
#pragma unroll
        for (int j = 0; j < 16; j++) {
            int i = lane + j * 32;
            float4 v = row[i];
            if (orow) orow[i] = v;
            float a = (v.x > LB_TH) ? v.x : 0.0f;
            float b = (v.y > LB_TH) ? v.y : 0.0f;
            float c = (v.z > LB_TH) ? v.z : 0.0f;
            float d = (v.w > LB_TH) ? v.w : 0.0f;
            mx = fmaxf(mx, fmaxf(fmaxf(a, b), fmaxf(c, d)));
            sq += a * a + b * b + c * c + d * d;
            wrow[2 * i]     = __floats2bfloat162_rn(-a, -b);
            wrow[2 * i + 1] = __floats2bfloat162_rn(-c, -d);
        }
#pragma unroll
        for (int s = 16; s > 0; s >>= 1) {
            mx = fmaxf(mx, __shfl_xor_sync(0xFFFFFFFF, mx, s));
            sq += __shfl_xor_sync(0xFFFFFFFF, sq, s);
        }
        if (lane == 0) g_rowterm[n] = mx + L2_LAMDA * sqrtf(sq);
    } else if (bid < INC_BLOCKS + R_BLOCKS) {
        const int g = (bid - INC_BLOCKS) * 256 + tid;
        float4 v0 = rproj[2 * g];
        float4 v1 = rproj[2 * g + 1];
        ((uint4*)g_r_bf)[g] = make_uint4(bf2u(v0.x, v0.y), bf2u(v0.z, v0.w),
                                         bf2u(v1.x, v1.y), bf2u(v1.z, v1.w));
    } else {
        int g = (bid - INC_BLOCKS - R_BLOCKS) * 256 + tid;
        const float4* src;
        uint4* dst;
        if (g < NG_BIG) { src = cur; dst = (uint4*)g_cur_bf; }
        else            { src = pre; dst = (uint4*)g_pre_bf; g -= NG_BIG; }
        float4 v0 = src[2 * g];
        float4 v1 = src[2 * g + 1];
        dst[g] = make_uint4(bf2u(v0.x, v0.y), bf2u(v0.z, v0.w),
                            bf2u(v1.x, v1.y), bf2u(v1.z, v1.w));
    }
}

// ---------------------------------------------------------------------------
// Main GEMM (R13/R15-proven config): per CTA (dtile, ntile, b),
// 128x128 tile: diff = cur_b @ R + (-W) @ pre_b
// 4 warps, each 64x64. 3-stage cp.async pipeline, ONE __syncthreads per chunk.
// ---------------------------------------------------------------------------
#define CHUNKS 36            // 4 (cur@R, K=256) + 32 (W@pre, K=2048)
#define STAGE_BYTES 32768    // 16KB A + 16KB B
#define NSTAGE 3
#define GEMM_SMEM (NSTAGE * STAGE_BYTES)   // 96KB; x2 CTAs = 192KB

__global__ __launch_bounds__(128, 2) void gemm_kernel() {
    extern __shared__ char smem[];
    const uint32_t sb = smem_u32(smem);
    const int tid = threadIdx.x;
    const int lane = tid & 31;
    const int w = tid >> 5;          // 0..3
    const int warp_m = w & 1;        // 64-row half
    const int warp_n = w >> 1;       // 64-col half

    const int dtile = blockIdx.x;    // 0..1
    const int ntile = blockIdx.y;    // 0..15
    const int b     = blockIdx.z;    // 0..31
    const int n0 = ntile * 128;
    const int d0 = dtile * 128;

    float acc[4][8][4];
#pragma unroll
    for (int mt = 0; mt < 4; mt++)
#pragma unroll
        for (int nt = 0; nt < 8; nt++)
#pragma unroll
            for (int i = 0; i < 4; i++) acc[mt][nt][i] = 0.0f;

    uint32_t arow[4];
#pragma unroll
    for (int mt = 0; mt < 4; mt++)
        arow[mt] = (uint32_t)(warp_m * 64 + mt * 16 + (lane & 15)) * 128;
    const uint32_t alx = (lane & 7);
    const uint32_t ahi = (lane >> 4);
    uint32_t btb[4];
#pragma unroll
    for (int jg = 0; jg < 4; jg++) {
        uint32_t cb = (uint32_t)(warp_n * 8 + jg * 2) + (lane >> 4);
        btb[jg] = (uint32_t)(lane & 15) * 256 + ((cb ^ (lane & 7)) << 4);
    }

    const __nv_bfloat16* curb = g_cur_bf + ((size_t)b * NN + n0) * DD;
    const __nv_bfloat16* preb = g_pre_bf + (size_t)b * NN * DD + d0;
    const __nv_bfloat16* wb   = g_w_bf + (size_t)n0 * NN;
    const __nv_bfloat16* rb   = g_r_bf + d0;

#define LOAD_KM(dst, src, ld)                                                   \
    _Pragma("unroll")                                                           \
    for (int i = 0; i < 8; i++) {                                               \
        int o = tid + i * 128;                                                  \
        int row = o >> 3, seg = o & 7;                                          \
        cp16((dst) + SWZ(row * 128 + seg * 16),                                 \
             (src) + (size_t)row * (ld) + seg * 8);                             \
    }
#define LOAD_TR(dst, src, ld)                                                   \
    _Pragma("unroll")                                                           \
    for (int i = 0; i < 8; i++) {                                               \
        int o = tid + i * 128;                                                  \
        int row = o >> 4, seg = o & 15;                                         \
        cp16((dst) + row * 256 + (((seg ^ (row & 7))) << 4),                    \
             (src) + (size_t)row * (ld) + seg * 8);                             \
    }

#define LOAD_CHUNK(c)                                                           \
    {                                                                           \
        const uint32_t st = sb + ((c) % NSTAGE) * STAGE_BYTES;                  \
        if ((c) < 4) {                                                          \
            int k0 = (c) * 64;                                                  \
            LOAD_KM(st, curb + k0, DD);                                         \
            LOAD_TR(st + 16384, rb + (size_t)k0 * DD, DD);                      \
        } else {                                                                \
            int k0 = ((c) - 4) * 64;                                            \
            LOAD_KM(st, wb + k0, NN);                                           \
            LOAD_TR(st + 16384, preb + (size_t)k0 * DD, DD);                    \
        }                                                                       \
        CP_COMMIT();                                                            \
    }

    LOAD_CHUNK(0);
    LOAD_CHUNK(1);

    for (int c = 0; c < CHUNKS; c++) {
        if (c + 1 < CHUNKS)
            asm volatile("cp.async.wait_group 1;" ::: "memory");
        else
            asm volatile("cp.async.wait_group 0;" ::: "memory");
        __syncthreads();

        if (c + 2 < CHUNKS) LOAD_CHUNK(c + 2);

        const uint32_t sA = sb + (uint32_t)(c % NSTAGE) * STAGE_BYTES;
        const uint32_t sB = sA + 16384;

#pragma unroll
        for (int s = 0; s < 4; s++) {
            const uint32_t ch = (uint32_t)(s * 2) + ahi;
            const uint32_t csw = (ch ^ alx) << 4;
            uint32_t a[4][4];
#pragma unroll
            for (int mt = 0; mt < 4; mt++)
                ldsm_x4(a[mt][0], a[mt][1], a[mt][2], a[mt][3],
                        sA + arow[mt] + csw);
            uint32_t bf[8][2];
#pragma unroll
            for (int jg = 0; jg < 4; jg++)
                ldsm_x4t(bf[2 * jg][0], bf[2 * jg][1],
                         bf[2 * jg + 1][0], bf[2 * jg + 1][1],
                         sB + s * 4096 + btb[jg]);
#pragma unroll
            for (int mt = 0; mt < 4; mt++)
#pragma unroll
                for (int nt = 0; nt < 8; nt++)
                    mma16816(acc[mt][nt], a[mt], bf[nt]);
        }
    }

    // ------------- epilogue: per-row sum of squares -------------
    __shared__ float red[128][2];
#pragma unroll
    for (int mt = 0; mt < 4; mt++) {
        float s0 = 0.0f, s1 = 0.0f;
#pragma unroll
        for (int nt = 0; nt < 8; nt++) {
            s0 = fmaf(acc[mt][nt][0], acc[mt][nt][0], s0);
            s0 = fmaf(acc[mt][nt][1], acc[mt][nt][1], s0);
            s1 = fmaf(acc[mt][nt][2], acc[mt][nt][2], s1);
            s1 = fmaf(acc[mt][nt][3], acc[mt][nt][3], s1);
        }
        s0 += __shfl_xor_sync(0xFFFFFFFF, s0, 1);
        s0 += __shfl_xor_sync(0xFFFFFFFF, s0, 2);
        s1 += __shfl_xor_sync(0xFFFFFFFF, s1, 1);
        s1 += __shfl_xor_sync(0xFFFFFFFF, s1, 2);
        if ((lane & 3) == 0) {
            int r = warp_m * 64 + mt * 16 + (lane >> 2);
            red[r][warp_n] = s0;
            red[r + 8][warp_n] = s1;
        }
    }
    __syncthreads();
    g_part[((size_t)dtile * BB + b) * NN + n0 + tid] = red[tid][0] + red[tid][1];
}

// ---------------------------------------------------------------------------
// Single finalize: 32 CTAs (one per b) x 1024 threads, 2 rows per thread.
// Each CTA also (redundantly, in identical order) reduces rowterm.
// out[b] = 0.2 * sum_n sqrt(part0+part1) + sum_n rowterm
// ---------------------------------------------------------------------------
__global__ __launch_bounds__(1024) void fin_kernel(float* __restrict__ out) {
    const int b = blockIdx.x;
    const int tid = threadIdx.x;
    const int lane = tid & 31;
    const int warp = tid >> 5;

    const float* p0 = g_part + (size_t)b * NN;
    const float* p1 = g_part + ((size_t)BB + b) * NN;

    float v = sqrtf(p0[tid] + p1[tid]) + sqrtf(p0[tid + 1024] + p1[tid + 1024]);
    float r = g_rowterm[tid] + g_rowterm[tid + 1024];

#pragma unroll
    for (int s = 16; s > 0; s >>= 1) {
        v += __shfl_xor_sync(0xFFFFFFFF, v, s);
        r += __shfl_xor_sync(0xFFFFFFFF, r, s);
    }
    __shared__ float sv[32];
    __shared__ float sr[32];
    if (lane == 0) { sv[warp] = v; sr[warp] = r; }
    __syncthreads();
    if (warp == 0) {
        float tv = sv[lane];
        float tr = sr[lane];
#pragma unroll
        for (int s = 16; s > 0; s >>= 1) {
            tv += __shfl_xor_sync(0xFFFFFFFF, tv, s);
            tr += __shfl_xor_sync(0xFFFFFFFF, tr, s);
        }
        if (lane == 0) out[b] = RECONS_LAMDA * tv + tr;
    }
}

// ---------------------------------------------------------------------------
extern "C" void kernel_launch(void* const* d_in, const int* in_sizes, int n_in,
                              void* d_out, int out_size) {
    const float* cur = nullptr;
    const float* pre = nullptr;
    const float* rproj = nullptr;
    const float* inc = nullptr;
    int big_seen = 0;
    for (int i = 0; i < n_in; i++) {
        if (in_sizes[i] == DD * DD) rproj = (const float*)d_in[i];
        else if (in_sizes[i] == NN * NN) inc = (const float*)d_in[i];
        else if (in_sizes[i] == BB * NN * DD) {
            if (big_seen == 0) cur = (const float*)d_in[i];
            else pre = (const float*)d_in[i];
            big_seen++;
        }
    }
    float* out = (float*)d_out;
    float* outinc = (out_size >= BB + NN * NN) ? (out + BB) : nullptr;

    cudaFuncSetAttribute(gemm_kernel, cudaFuncAttributeMaxDynamicSharedMemorySize, GEMM_SMEM);

    prep_kernel<<<PREP_GRID, 256>>>((const float4*)cur, (const float4*)pre,
                                    (const float4*)rproj, inc, outinc);       // 1
    gemm_kernel<<<dim3(2, 16, BB), 128, GEMM_SMEM>>>();                       // 2
    fin_kernel<<<BB, 1024>>>(out);                                            // 3
}